// round 2
// baseline (speedup 1.0000x reference)
#include <cuda_runtime.h>
#include <cstdint>

#define FULLM 0xffffffffu

namespace {
constexpr int   T_STEPS = 128;
constexpr int   NCH = 17;
constexpr int   REC_F4 = (32 * NCH) / 4;   // 136 float4 per 32-record chunk
constexpr int   WARPS_PER_BLOCK = 4;
}

// Inclusive scan over 32 per-lane block values with JAX associative_scan
// association (Brent-Kung odd/even recursion, combine(left, right) order).
__device__ __forceinline__ float jax_scan32(float r, int lane) {
    // upsweep: reduced = combine(even, odd)
#pragma unroll
    for (int h = 1; h <= 16; h <<= 1) {
        float u = __shfl_up_sync(FULLM, r, h);
        if ((lane & (2 * h - 1)) == (2 * h - 1)) r = __fadd_rn(u, r);
    }
    // downsweep: even = combine(odd_scanned, elem)
#pragma unroll
    for (int h = 8; h >= 1; h >>= 1) {
        float u = __shfl_up_sync(FULLM, r, h);
        if (lane >= 2 * h && (lane & (2 * h - 1)) == (h - 1)) r = __fadd_rn(u, r);
    }
    return r;
}

// Full-T (128) inclusive scan, JAX association. Lane L owns t = 4L..4L+3.
__device__ __forceinline__ void scan128(const float a[4], float s[4], int lane) {
    const float p = __fadd_rn(a[0], a[1]);
    const float q = __fadd_rn(a[2], a[3]);
    const float r = __fadd_rn(p, q);
    const float S = jax_scan32(r, lane);
    const float E = __shfl_up_sync(FULLM, S, 1);   // exclusive (garbage on lane 0)
    if (lane == 0) {
        s[0] = a[0];
        s[1] = p;
        s[2] = __fadd_rn(p, a[2]);
        s[3] = S;
    } else {
        s[0] = __fadd_rn(E, a[0]);
        s[1] = __fadd_rn(E, p);
        s[2] = __fadd_rn(s[1], a[2]);
        s[3] = S;
    }
}

__global__ __launch_bounds__(WARPS_PER_BLOCK * 32)
void car_dyn_kernel(const float* __restrict__ state,
                    const float* __restrict__ pact,
                    const float* __restrict__ Hmap,
                    const float* __restrict__ Nrm,
                    float* __restrict__ out_states,
                    float* __restrict__ out_pa,
                    int K)
{
    __shared__ float buf[WARPS_PER_BLOCK * 32 * NCH];

    const int wid  = threadIdx.x >> 5;
    const int lane = threadIdx.x & 31;
    const int k    = blockIdx.x * WARPS_PER_BLOCK + wid;
    if (k >= K) return;

    float*  sb  = buf + wid * (32 * NCH);
    float4* sb4 = reinterpret_cast<float4*>(sb);

    const float4* src  = reinterpret_cast<const float4*>(state + (size_t)k * T_STEPS * NCH);
    const float4* pin4 = reinterpret_cast<const float4*>(pact)  + (size_t)k * (T_STEPS / 2);
    float4*       dst4 = reinterpret_cast<float4*>(out_states + (size_t)k * T_STEPS * NCH);
    float4*       op4  = reinterpret_cast<float4*>(out_pa)     + (size_t)k * (T_STEPS / 2);

    // ---- perturbed actions: lane L owns t = 4L..4L+3, coalesced float4 ----
    const float4 pA = pin4[2 * lane];
    const float4 pB = pin4[2 * lane + 1];
    float pax[4] = {pA.x, pA.z, pB.x, pB.z};
    float pay[4] = {pA.y, pA.w, pB.y, pB.w};

    // ---- stage state channels (4 chunk rounds, coalesced) ----
    float s0v[4], s1v[4], s5v[4], s9v[4], s15v[4], s16v[4];
    float s12v = 0.f, s13v = 0.f;
#pragma unroll
    for (int c = 0; c < 4; ++c) {
#pragma unroll
        for (int i = 0; i < 5; ++i) {
            int j = lane + 32 * i;
            if (j < REC_F4) sb4[j] = src[c * REC_F4 + j];
        }
        __syncwarp();
        if ((lane >> 3) == c) {
            const int rbase = (lane & 7) * 4 * NCH;
#pragma unroll
            for (int m = 0; m < 4; ++m) {
                const float* rec = sb + rbase + m * NCH;
                s0v[m]  = rec[0];  s1v[m]  = rec[1];
                s5v[m]  = rec[5];  s9v[m]  = rec[9];
                s15v[m] = rec[15]; s16v[m] = rec[16];
            }
            if (lane == 0 && c == 0) { s12v = sb[12]; s13v = sb[13]; }
        }
        __syncwarp();
    }

    // ---- stage 1: controls = clip(ctrl0 + 4*cumsum(pa*DT)) ----
    float t0[4], t1[4];
#pragma unroll
    for (int m = 0; m < 4; ++m) {
        t0[m] = __fmul_rn(pax[m], 0.02f);
        t1[m] = __fmul_rn(pay[m], 0.02f);
    }
    float cs0[4], cs1[4];
    scan128(t0, cs0, lane);
    scan128(t1, cs1, lane);

    float steer[4], thr[4], cm0[4], cm1[4];
#pragma unroll
    for (int m = 0; m < 4; ++m) {
        float c0 = fminf(fmaxf(__fadd_rn(s15v[m], __fmul_rn(4.0f, cs0[m])), -1.f), 1.f);
        float c1 = fminf(fmaxf(__fadd_rn(s16v[m], __fmul_rn(4.0f, cs1[m])), -1.f), 1.f);
        c1 = fminf(fmaxf(c1, 0.f), 0.5f);
        steer[m] = c0; thr[m] = c1;
        cm0[m] = __fsub_rn(c0, s15v[m]);
        cm1[m] = __fsub_rn(c1, s16v[m]);
    }

    // ---- new_pa: t=0 -> raw pa; else diff(cm)/0.08f ----
    const float pcm0 = __shfl_up_sync(FULLM, cm0[3], 1);
    const float pcm1 = __shfl_up_sync(FULLM, cm1[3], 1);
    float np0[4], np1[4];
#pragma unroll
    for (int m = 0; m < 4; ++m) {
        const float pm0 = m ? cm0[m - 1] : pcm0;
        const float pm1 = m ? cm1[m - 1] : pcm1;
        np0[m] = __fdiv_rn(__fsub_rn(cm0[m], pm0), 0.08f);
        np1[m] = __fdiv_rn(__fsub_rn(cm1[m], pm1), 0.08f);
    }
    if (lane == 0) { np0[0] = pax[0]; np1[0] = pay[0]; }

    // ---- dynamics elementwise ----
    float vx[4], dS[4], wzv[4];
#pragma unroll
    for (int m = 0; m < 4; ++m) {
        const float Kc = __fdiv_rn(tanf(steer[m]), 0.5f);
        vx[m] = __fmul_rn(thr[m], 17.0f);
        dS[m] = __fmul_rn(vx[m], 0.02f);
        const float w1 = __fmul_rn(vx[m], Kc);
        const float a0 = fminf(fmaxf(__fmul_rn(vx[m], w1), -14.f), 14.f);
        wzv[m] = __fdiv_rn(a0, fminf(fmaxf(vx[m], 1.f), 25.f));
    }

    // ---- stage 2: yaw = s5 + DT*cumsum(wz) ----
    float cwz[4];
    scan128(wzv, cwz, lane);
    float yaw[4], cyv[4], syv[4];
#pragma unroll
    for (int m = 0; m < 4; ++m) {
        yaw[m] = __fadd_rn(s5v[m], __fmul_rn(0.02f, cwz[m]));
        cyv[m] = cosf(yaw[m]);
        syv[m] = sinf(yaw[m]);
    }

    // ---- stage 3: x,y ----
    float tx[4], ty[4];
#pragma unroll
    for (int m = 0; m < 4; ++m) {
        tx[m] = __fmul_rn(dS[m], cyv[m]);
        ty[m] = __fmul_rn(dS[m], syv[m]);
    }
    float cx[4], cyy[4];
    scan128(tx, cx, lane);
    scan128(ty, cyy, lane);
    float xv[4], yv[4];
#pragma unroll
    for (int m = 0; m < 4; ++m) {
        xv[m] = __fadd_rn(s0v[m], cx[m]);
        yv[m] = __fadd_rn(s1v[m], cyy[m]);
    }

    // ---- BEV gather + roll/pitch ----
    float zv[4], rollv[4], pitchv[4], nzv[4];
#pragma unroll
    for (int m = 0; m < 4; ++m) {
        int iX = (int)(__fmul_rn(__fadd_rn(xv[m], 32.f), 4.f));
        int iY = (int)(__fmul_rn(__fadd_rn(yv[m], 32.f), 4.f));
        iX = min(max(iX, 0), 255);
        iY = min(max(iY, 0), 255);
        const int g = iY * 256 + iX;
        zv[m] = Hmap[g];
        const float nx = Nrm[3 * g + 0];
        const float ny = Nrm[3 * g + 1];
        const float nz = Nrm[3 * g + 2];
        nzv[m] = nz;
        // left = cross(normal, heading); heading = (cy, sy, 0)
        const float lz = __fsub_rn(__fmul_rn(nx, syv[m]), __fmul_rn(ny, cyv[m]));
        const float lx = __fsub_rn(0.f, __fmul_rn(nz, syv[m]));   // ny*0 - nz*sy
        const float ly = __fmul_rn(nz, cyv[m]);                   // nz*cy - nx*0
        rollv[m] = asinf(lz);
        // fwd = cross(left, normal); fwd.z = lx*ny - ly*nx
        const float fz = __fsub_rn(__fmul_rn(lx, ny), __fmul_rn(ly, nx));
        pitchv[m] = -asinf(fz);
    }

    // ---- wx, wy, ay, az ----
    const float proll  = __shfl_up_sync(FULLM, rollv[3], 1);
    const float ppitch = __shfl_up_sync(FULLM, pitchv[3], 1);
    float wx[4], wy[4], ayv[4], azv[4];
#pragma unroll
    for (int m = 0; m < 4; ++m) {
        const float pr = m ? rollv[m - 1]  : proll;
        const float pp = m ? pitchv[m - 1] : ppitch;
        wx[m] = __fdiv_rn(__fsub_rn(rollv[m],  pr), 0.02f);
        wy[m] = __fdiv_rn(__fsub_rn(pitchv[m], pp), 0.02f);
    }
    if (lane == 0) { wx[0] = s12v; wy[0] = s13v; }
#pragma unroll
    for (int m = 0; m < 4; ++m) {
        ayv[m] = __fadd_rn(__fmul_rn(vx[m], wzv[m]), __fmul_rn(9.8f, sinf(rollv[m])));
        azv[m] = __fadd_rn(__fmul_rn(__fsub_rn(0.f, vx[m]), wy[m]), __fmul_rn(9.8f, nzv[m]));
    }

    // ---- write states via smem (coalesced float4), 4 chunk rounds ----
#pragma unroll
    for (int c = 0; c < 4; ++c) {
        __syncwarp();
        if ((lane >> 3) == c) {
            const int rbase = (lane & 7) * 4 * NCH;
#pragma unroll
            for (int m = 0; m < 4; ++m) {
                float* rec = sb + rbase + m * NCH;
                rec[0]  = xv[m];     rec[1]  = yv[m];
                rec[2]  = zv[m];     rec[3]  = rollv[m];
                rec[4]  = pitchv[m]; rec[5]  = yaw[m];
                rec[6]  = vx[m];     rec[7]  = 0.f;
                rec[8]  = 0.f;       rec[9]  = s9v[m];
                rec[10] = ayv[m];    rec[11] = azv[m];
                rec[12] = wx[m];     rec[13] = wy[m];
                rec[14] = wzv[m];    rec[15] = steer[m];
                rec[16] = thr[m];
            }
        }
        __syncwarp();
#pragma unroll
        for (int i = 0; i < 5; ++i) {
            int j = lane + 32 * i;
            if (j < REC_F4) dst4[c * REC_F4 + j] = sb4[j];
        }
    }

    // ---- new_pa out, coalesced float4 ----
    op4[2 * lane]     = make_float4(np0[0], np1[0], np0[1], np1[1]);
    op4[2 * lane + 1] = make_float4(np0[2], np1[2], np0[3], np1[3]);
}

extern "C" void kernel_launch(void* const* d_in, const int* in_sizes, int n_in,
                              void* d_out, int out_size)
{
    const float* state = (const float*)d_in[0];
    const float* pact  = (const float*)d_in[1];
    const float* Hmap  = (const float*)d_in[2];
    const float* Nrm   = (const float*)d_in[3];

    const int K = (in_sizes[1] / 2) / T_STEPS;
    float* out_states = (float*)d_out;
    float* out_pa     = (float*)d_out + (size_t)in_sizes[0];

    const int blocks = (K + WARPS_PER_BLOCK - 1) / WARPS_PER_BLOCK;
    car_dyn_kernel<<<blocks, WARPS_PER_BLOCK * 32>>>(state, pact, Hmap, Nrm,
                                                     out_states, out_pa, K);
}